// round 2
// baseline (speedup 1.0000x reference)
#include <cuda_runtime.h>
#include <cuda_bf16.h>

// GHMC loss, single streaming pass.
// loss = (1/n_nonempty) * sum_b ( bce_sum[b] / count[b] )   over nonempty bins
// where per element: z = sigmoid(pred); g = |z - t|; b = min((int)(g*10), 9);
//                    bce = log(1 + e^z) - t*z   (softplus(z) - t*z)

#define BINS 10
#define THREADS 256
#define GRID 1184          // 148 SMs * 8 blocks

// Per-block partials (deterministic: every slot written every launch).
__device__ double             g_part_sum[GRID * BINS];
__device__ unsigned long long g_part_cnt[GRID * BINS];

__global__ __launch_bounds__(THREADS, 8)
void ghmc_main_kernel(const float4* __restrict__ pred4,
                      const int4*   __restrict__ tgt4,
                      int nvec,                    // number of float4 groups
                      const float*  __restrict__ pred,
                      const int*    __restrict__ tgt,
                      int ntotal)
{
    // Privatized per-thread bins in shared: layout [bin][tid] -> bank = tid%32,
    // conflict-free read-modify-write, no atomics.
    __shared__ float        s_sum[BINS * THREADS];
    __shared__ unsigned int s_cnt[BINS * THREADS];

    const int tid = threadIdx.x;
#pragma unroll
    for (int b = 0; b < BINS; ++b) {
        s_sum[b * THREADS + tid] = 0.0f;
        s_cnt[b * THREADS + tid] = 0u;
    }
    __syncthreads();

    const int stride = GRID * THREADS;

    auto process = [&](float x, int t) {
        float tf = (float)t;
        float u  = __expf(-x);
        float z  = __fdividef(1.0f, 1.0f + u);      // sigmoid(pred)
        float g  = fabsf(z - tf);                   // gradient magnitude
        int   b  = (int)(g * 10.0f);
        b = b > (BINS - 1) ? (BINS - 1) : b;        // g <= 1 => b in [0, 9]
        float ez  = __expf(z);
        float bce = __logf(1.0f + ez) - tf * z;     // softplus(z) - t*z
        s_sum[b * THREADS + tid] += bce;
        s_cnt[b * THREADS + tid] += 1u;
    };

    // Vectorized main loop: 16B per thread per array.
    for (int i = blockIdx.x * THREADS + tid; i < nvec; i += stride) {
        float4 p = pred4[i];
        int4   t = tgt4[i];
        process(p.x, t.x);
        process(p.y, t.y);
        process(p.z, t.z);
        process(p.w, t.w);
    }

    // Scalar tail (block 0 only).
    if (blockIdx.x == 0) {
        for (int i = nvec * 4 + tid; i < ntotal; i += THREADS)
            process(pred[i], tgt[i]);
    }

    __syncthreads();

    // Block reduction: warp w handles bins w and w+8. Fixed order => deterministic.
    const int wid  = tid >> 5;
    const int lane = tid & 31;
    for (int b = wid; b < BINS; b += 8) {
        float        s = 0.0f;
        unsigned int c = 0u;
#pragma unroll
        for (int i = lane; i < THREADS; i += 32) {
            s += s_sum[b * THREADS + i];
            c += s_cnt[b * THREADS + i];
        }
#pragma unroll
        for (int off = 16; off; off >>= 1) {
            s += __shfl_down_sync(0xffffffffu, s, off);
            c += __shfl_down_sync(0xffffffffu, c, off);
        }
        if (lane == 0) {
            g_part_sum[blockIdx.x * BINS + b] = (double)s;
            g_part_cnt[blockIdx.x * BINS + b] = (unsigned long long)c;
        }
    }
}

__global__ void ghmc_finalize_kernel(float* __restrict__ out)
{
    __shared__ double             fin_sum[BINS];
    __shared__ unsigned long long fin_cnt[BINS];

    const int wid  = threadIdx.x >> 5;   // 10 warps, one per bin
    const int lane = threadIdx.x & 31;

    if (wid < BINS) {
        double             s = 0.0;
        unsigned long long c = 0ull;
        for (int i = lane; i < GRID; i += 32) {
            s += g_part_sum[i * BINS + wid];
            c += g_part_cnt[i * BINS + wid];
        }
#pragma unroll
        for (int off = 16; off; off >>= 1) {
            s += __shfl_down_sync(0xffffffffu, s, off);
            c += __shfl_down_sync(0xffffffffu, c, off);
        }
        if (lane == 0) { fin_sum[wid] = s; fin_cnt[wid] = c; }
    }
    __syncthreads();

    if (threadIdx.x == 0) {
        double loss = 0.0;
        int    n_ne = 0;
#pragma unroll
        for (int b = 0; b < BINS; ++b) {
            if (fin_cnt[b] > 0ull) {
                ++n_ne;
                loss += fin_sum[b] / (double)fin_cnt[b];
            }
        }
        if (n_ne < 1) n_ne = 1;
        out[0] = (float)(loss / (double)n_ne);
    }
}

extern "C" void kernel_launch(void* const* d_in, const int* in_sizes, int n_in,
                              void* d_out, int out_size)
{
    const float* pred = (const float*)d_in[0];
    const int*   tgt  = (const int*)d_in[1];
    float*       out  = (float*)d_out;
    const int n    = in_sizes[0];
    const int nvec = n >> 2;

    ghmc_main_kernel<<<GRID, THREADS>>>((const float4*)pred, (const int4*)tgt,
                                        nvec, pred, tgt, n);
    ghmc_finalize_kernel<<<1, 320>>>(out);
}

// round 3
// speedup vs baseline: 1.0537x; 1.0537x over previous
#include <cuda_runtime.h>
#include <cuda_bf16.h>

// GHMC loss, single streaming pass + in-kernel atomic reduction.
// loss = (1/n_nonempty) * sum_b ( bce_sum[b] / count[b] )
// per element: z = sigmoid(pred); g = |z - t|; b = min((int)(g*10), 9);
//              bce = log(1 + e^z) - t*z
//
// Determinism: per-block partials are reduced in a fixed order, converted to
// fixed-point (2^-30) u64, and combined with integer atomics (associative ->
// bit-exact regardless of arrival order). The finalize kernel reads the
// accumulators, writes the loss, then RESETS them to zero so every graph
// replay starts from the same state (device globals are zero at module load).

#define BINS 10
#define THREADS 256
#define GRID 1184          // 148 SMs * 8 blocks
#define FIX_SCALE 1073741824.0   // 2^30

__device__ unsigned long long g_bin_sum[BINS];   // fixed-point 2^-30
__device__ unsigned long long g_bin_cnt[BINS];

__global__ __launch_bounds__(THREADS, 8)
void ghmc_main_kernel(const float4* __restrict__ pred4,
                      const int4*   __restrict__ tgt4,
                      int nvec,                    // number of float4 groups
                      const float*  __restrict__ pred,
                      const int*    __restrict__ tgt,
                      int ntotal)
{
    // Privatized per-thread bins in shared: layout [bin][tid] -> bank = tid%32,
    // conflict-free read-modify-write, no atomics in the hot loop.
    __shared__ float        s_sum[BINS * THREADS];
    __shared__ unsigned int s_cnt[BINS * THREADS];

    const int tid = threadIdx.x;
#pragma unroll
    for (int b = 0; b < BINS; ++b) {
        s_sum[b * THREADS + tid] = 0.0f;
        s_cnt[b * THREADS + tid] = 0u;
    }
    __syncthreads();

    const int stride = GRID * THREADS;

    auto process = [&](float x, int t) {
        float tf = (float)t;
        float u  = __expf(-x);
        float z  = __fdividef(1.0f, 1.0f + u);      // sigmoid(pred)
        float g  = fabsf(z - tf);                   // gradient magnitude
        int   b  = (int)(g * 10.0f);
        b = b > (BINS - 1) ? (BINS - 1) : b;        // g <= 1 => b in [0, 9]
        float ez  = __expf(z);
        float bce = __logf(1.0f + ez) - tf * z;     // softplus(z) - t*z
        s_sum[b * THREADS + tid] += bce;
        s_cnt[b * THREADS + tid] += 1u;
    };

    // Vectorized main loop: 16B per thread per array.
    for (int i = blockIdx.x * THREADS + tid; i < nvec; i += stride) {
        float4 p = pred4[i];
        int4   t = tgt4[i];
        process(p.x, t.x);
        process(p.y, t.y);
        process(p.z, t.z);
        process(p.w, t.w);
    }

    // Scalar tail (block 0 only).
    if (blockIdx.x == 0) {
        for (int i = nvec * 4 + tid; i < ntotal; i += THREADS)
            process(pred[i], tgt[i]);
    }

    __syncthreads();

    // Block reduction: warp w handles bins w and w+8 (fixed order), then a
    // single fixed-point integer atomic per bin -> order-independent result.
    const int wid  = tid >> 5;
    const int lane = tid & 31;
    for (int b = wid; b < BINS; b += 8) {
        float        s = 0.0f;
        unsigned int c = 0u;
#pragma unroll
        for (int i = lane; i < THREADS; i += 32) {
            s += s_sum[b * THREADS + i];
            c += s_cnt[b * THREADS + i];
        }
#pragma unroll
        for (int off = 16; off; off >>= 1) {
            s += __shfl_down_sync(0xffffffffu, s, off);
            c += __shfl_down_sync(0xffffffffu, c, off);
        }
        if (lane == 0) {
            unsigned long long sfix =
                (unsigned long long)__double2ll_rn((double)s * FIX_SCALE);
            atomicAdd(&g_bin_sum[b], sfix);
            atomicAdd(&g_bin_cnt[b], (unsigned long long)c);
        }
    }
}

__global__ void ghmc_finalize_kernel(float* __restrict__ out)
{
    if (threadIdx.x == 0) {
        double loss = 0.0;
        int    n_ne = 0;
#pragma unroll
        for (int b = 0; b < BINS; ++b) {
            unsigned long long c = g_bin_cnt[b];
            unsigned long long s = g_bin_sum[b];
            if (c > 0ull) {
                ++n_ne;
                loss += ((double)s / FIX_SCALE) / (double)c;
            }
        }
        if (n_ne < 1) n_ne = 1;
        out[0] = (float)(loss / (double)n_ne);
    }
    // Reset accumulators for the next execution (graph replay / re-validation).
    if (threadIdx.x < BINS) {
        g_bin_sum[threadIdx.x] = 0ull;
        g_bin_cnt[threadIdx.x] = 0ull;
    }
}

extern "C" void kernel_launch(void* const* d_in, const int* in_sizes, int n_in,
                              void* d_out, int out_size)
{
    const float* pred = (const float*)d_in[0];
    const int*   tgt  = (const int*)d_in[1];
    float*       out  = (float*)d_out;
    const int n    = in_sizes[0];
    const int nvec = n >> 2;

    ghmc_main_kernel<<<GRID, THREADS>>>((const float4*)pred, (const int4*)tgt,
                                        nvec, pred, tgt, n);
    ghmc_finalize_kernel<<<1, 32>>>(out);
}